// round 11
// baseline (speedup 1.0000x reference)
#include <cuda_runtime.h>

#define NQ      14
#define DIM     (1 << NQ)       // 16384 amplitudes
#define HALF    (DIM / 2)       // 8192 packed u64 per plane
#define NL      8
#define NGATES  ((NL + 1) * NQ) // 126 single-qubit gates
#define THREADS 1024

typedef unsigned long long u64;

// XOR swizzle on u64-plane index (bijective: only low 4 bits modified by
// higher bits). Folds BOTH bit-groups 4..7 and 9..12 into the bank bits so
// every pass layout (incl. pass C whose lane bits sit at p bits 10..12) is
// conflict-free per half-warp.
__device__ __forceinline__ int phys64(int p) {
    return p ^ ((p >> 4) & 15) ^ ((p >> 9) & 15);
}

__device__ __forceinline__ u64 pk2(float lo, float hi) {
    u64 r; asm("mov.b64 %0, {%1,%2};" : "=l"(r) : "f"(lo), "f"(hi)); return r;
}
__device__ __forceinline__ void upk2(u64 v, float& lo, float& hi) {
    asm("mov.b64 {%0,%1}, %2;" : "=f"(lo), "=f"(hi) : "l"(v));
}
__device__ __forceinline__ u64 swap2(u64 v) {
    float lo, hi; upk2(v, lo, hi); return pk2(hi, lo);
}
__device__ __forceinline__ u64 fma2(u64 a, u64 b, u64 c) {
    u64 d; asm("fma.rn.f32x2 %0, %1, %2, %3;" : "=l"(d) : "l"(a), "l"(b), "l"(c));
    return d;
}
__device__ __forceinline__ u64 mul2(u64 a, u64 b) {
    u64 d; asm("mul.rn.f32x2 %0, %1, %2;" : "=l"(d) : "l"(a), "l"(b));
    return d;
}

// ---- Rx butterflies (real coefficients c = cos(qx/2), s = sin(qx/2))
// new0: x = c*x0 + s*y1 ; y = c*y0 - s*x1
// new1: x = c*x1 + s*y0 ; y = c*y1 - s*x0

// Broadcast: partners are distinct packed elements (bit BIT of j, 8 elements).
template<int BIT>
__device__ __forceinline__ void rx_bcast(u64* PX, u64* PY, float2 g) {
    const u64 C  = pk2(g.x,  g.x);
    const u64 Sp = pk2(g.y,  g.y);
    const u64 Sn = pk2(-g.y, -g.y);
    #pragma unroll
    for (int j = 0; j < 8; j++) {
        if (j & (1 << BIT)) continue;
        const int j2 = j | (1 << BIT);
        u64 x0 = PX[j], y0 = PY[j], x1 = PX[j2], y1 = PY[j2];
        PX[j]  = fma2(C, x0, mul2(Sp, y1));
        PY[j]  = fma2(C, y0, mul2(Sn, x1));
        PX[j2] = fma2(C, x1, mul2(Sp, y0));
        PY[j2] = fma2(C, y1, mul2(Sn, x0));
    }
}

// Pair-form: partners are the two lanes of each packed element.
__device__ __forceinline__ void rx_pair(u64* PX, u64* PY, float2 g) {
    const u64 C  = pk2(g.x,  g.x);
    const u64 Sp = pk2(g.y,  g.y);
    const u64 Sn = pk2(-g.y, -g.y);
    #pragma unroll
    for (int j = 0; j < 8; j++) {
        u64 px = PX[j], py = PY[j];
        u64 sxw = swap2(px), syw = swap2(py);
        PX[j] = fma2(C, px, mul2(Sp, syw));
        PY[j] = fma2(C, py, mul2(Sn, sxw));
    }
}

// Shuffle-form: partners sit in lane (tid ^ mask) of the same warp.
// Symmetric for both sides: x' = c*x + s*y_partner ; y' = c*y - s*x_partner.
__device__ __forceinline__ void rx_shfl(u64* PX, u64* PY, float2 g, int mask) {
    const u64 C  = pk2(g.x,  g.x);
    const u64 Sp = pk2(g.y,  g.y);
    const u64 Sn = pk2(-g.y, -g.y);
    #pragma unroll
    for (int j = 0; j < 8; j++) {
        u64 xp = __shfl_xor_sync(0xffffffffu, PX[j], mask);
        u64 yp = __shfl_xor_sync(0xffffffffu, PY[j], mask);
        PX[j] = fma2(C, PX[j], mul2(Sp, yp));
        PY[j] = fma2(C, PY[j], mul2(Sn, xp));
    }
}

// One CTA = one (batch, circuit) pair; 1024 threads, 8 packed pairs each.
// Layer = Gray-fused gather + pass A (wires 13..10) + pass B (9..6) +
// pass C (5..3 bcast, 2..0 shuffle, merged Rz diagonal).
__global__ void __launch_bounds__(THREADS, 1)
pqc_kernel(const float* __restrict__ x,
           const float* __restrict__ qx1, const float* __restrict__ qz1,
           const float* __restrict__ c1,
           const float* __restrict__ qx2, const float* __restrict__ qz2,
           const float* __restrict__ c2,
           float* __restrict__ out, int B)
{
    extern __shared__ u64 dsm[];            // 2 * HALF u64 = 128 KB
    u64* SX = dsm;
    u64* SY = dsm + HALF;
    __shared__ float2 U2[NGATES];           // (cos(qx/2), sin(qx/2))
    __shared__ float  qzh[NGATES];          // qz/2
    __shared__ float2 ejt[8];               // per-layer j-part phase table
    __shared__ float  csh[NQ];
    __shared__ float  amp[NQ][2];
    __shared__ float  wsum[THREADS / 32];

    const int tid  = threadIdx.x;
    const int b    = blockIdx.x;
    const int circ = blockIdx.y;

    const float* qx = circ ? qx2 : qx1;
    const float* qz = circ ? qz2 : qz1;
    const float* cc = circ ? c2  : c1;

    if (tid < NGATES) {
        float ax = 0.5f * qx[tid];
        U2[tid]  = make_float2(cosf(ax), sinf(ax));
        qzh[tid] = 0.5f * qz[tid];
    }
    if (tid < NQ) {
        csh[tid] = cc[tid];
        float bit = (x[b * NQ + tid] > 0.0f) ? 1.0f : 0.0f;
        float th = 1.5707963705062866f * bit;    // 0.5f * float32(pi) * bit
        amp[tid][0] = cosf(th);
        amp[tid][1] = sinf(th);
    }
    __syncthreads();

    const int wrp = tid >> 5;               // warp id (5 bits)
    const int L   = tid & 31;               // lane

    u64 PX[8], PY[8];
    float local = 0.0f;

    for (int l = 0; l <= NL; l++) {
        const int gb = l * NQ;

        // ===== Pass A: i = (tid<<4)|(j<<1)|pb. pb=wire13, j bits->wires 12,11,10
        if (l == 0) {
            float ph = 1.0f;
            #pragma unroll
            for (int w = 0; w < 10; w++)
                ph *= amp[w][(tid >> (9 - w)) & 1];
            const float a13_0 = amp[13][0], a13_1 = amp[13][1];
            #pragma unroll
            for (int j = 0; j < 8; j++) {
                float pj = ph;
                #pragma unroll
                for (int w = 10; w < 13; w++)
                    pj *= amp[w][(j >> (12 - w)) & 1];
                PX[j] = pk2(pj * a13_0, pj * a13_1);
                PY[j] = 0ULL;
            }
        } else {
            // Gray gather: pair slot m <- slot m^(m>>1), lane-swap if odd src
            #pragma unroll
            for (int j = 0; j < 8; j++) {
                int m  = (tid << 3) | j;
                int ps = m ^ (m >> 1);
                u64 vx = SX[phys64(ps)], vy = SY[phys64(ps)];
                if (j & 1) { vx = swap2(vx); vy = swap2(vy); }
                PX[j] = vx; PY[j] = vy;
            }
        }
        rx_pair(PX, PY, U2[gb + 13]);
        rx_bcast<0>(PX, PY, U2[gb + 12]);
        rx_bcast<1>(PX, PY, U2[gb + 11]);
        rx_bcast<2>(PX, PY, U2[gb + 10]);
        if (l > 0) __syncthreads();          // WAR: all gathers read first
        #pragma unroll
        for (int j = 0; j < 8; j++) {
            int m = (tid << 3) | j;
            SX[phys64(m)] = PX[j]; SY[phys64(m)] = PY[j];
        }
        __syncthreads();

        // ===== Pass B: i = (thi<<8)|(j<<5)|(pb<<4)|tlo. pb=wire9, j->8,7,6
        {
            const int thi = tid >> 4, tlo = tid & 15;
            const int fbit = tlo & 1;
            const int pbase = (thi << 7) | (tlo >> 1);
            const float* fx = (const float*)SX;
            const float* fy = (const float*)SY;
            #pragma unroll
            for (int j = 0; j < 8; j++) {
                int p0 = pbase | (j << 4);
                int p1 = p0 | 8;
                int a0 = 2 * phys64(p0) + fbit, a1 = 2 * phys64(p1) + fbit;
                PX[j] = pk2(fx[a0], fx[a1]);
                PY[j] = pk2(fy[a0], fy[a1]);
            }
            rx_pair(PX, PY, U2[gb + 9]);
            rx_bcast<0>(PX, PY, U2[gb + 8]);
            rx_bcast<1>(PX, PY, U2[gb + 7]);
            rx_bcast<2>(PX, PY, U2[gb + 6]);
            __syncthreads();                 // WAR
            float* fxw = (float*)SX;
            float* fyw = (float*)SY;
            #pragma unroll
            for (int j = 0; j < 8; j++) {
                int p0 = pbase | (j << 4);
                int p1 = p0 | 8;
                int a0 = 2 * phys64(p0) + fbit, a1 = 2 * phys64(p1) + fbit;
                float xl, xh, yl, yh;
                upk2(PX[j], xl, xh); upk2(PY[j], yl, yh);
                fxw[a0] = xl; fxw[a1] = xh; fyw[a0] = yl; fyw[a1] = yh;
            }
            // per-layer j-part phase table (wires 5,4,3 <-> pass-C j bits 0,1,2)
            if (l < NL && tid < 8) {
                float a = 0.0f;
                #pragma unroll
                for (int t = 0; t < 3; t++)
                    a += ((tid >> t) & 1) ? qzh[gb + 5 - t] : -qzh[gb + 5 - t];
                ejt[tid] = make_float2(cosf(a), sinf(a));
            }
            __syncthreads();                 // RAW for pass C (state + table)
        }

        // ===== Pass C: p = (L0<<12)|(L1<<11)|(L2<<10)|(j<<7)|(w<<2)|(L4<<1)|L3
        // i = 2p|pb. pb=wire13? no: pb=bit0=wire13 already gated -> ungated here.
        // j bits -> wires 5,4,3 (bcast); L2,L1,L0 -> wires 2,1,0 (shuffle).
        {
            const int baseC = ((L & 1) << 12) | (((L >> 1) & 1) << 11) |
                              (((L >> 2) & 1) << 10) | (wrp << 2) |
                              (((L >> 4) & 1) << 1) | ((L >> 3) & 1);
            #pragma unroll
            for (int j = 0; j < 8; j++) {
                int p = baseC | (j << 7);
                PX[j] = SX[phys64(p)]; PY[j] = SY[phys64(p)];
            }
            rx_bcast<0>(PX, PY, U2[gb + 5]);
            rx_bcast<1>(PX, PY, U2[gb + 4]);
            rx_bcast<2>(PX, PY, U2[gb + 3]);
            rx_shfl(PX, PY, U2[gb + 2], 4);  // wire 2 <-> lane bit 2
            rx_shfl(PX, PY, U2[gb + 1], 2);  // wire 1 <-> lane bit 1
            rx_shfl(PX, PY, U2[gb + 0], 1);  // wire 0 <-> lane bit 0

            if (l < NL) {
                // Merged Rz diagonal. Thread part: wires 12(L3) 11(L4)
                // 10..6(warp bits) 2(L2) 1(L1) 0(L0); packed-lane: wire 13.
                float pht = 0.0f;
                pht += ((L >> 3) & 1) ? qzh[gb + 12] : -qzh[gb + 12];
                pht += ((L >> 4) & 1) ? qzh[gb + 11] : -qzh[gb + 11];
                #pragma unroll
                for (int t = 0; t < 5; t++)
                    pht += ((wrp >> t) & 1) ? qzh[gb + 10 - t] : -qzh[gb + 10 - t];
                pht += ((L >> 2) & 1) ? qzh[gb + 2] : -qzh[gb + 2];
                pht += ((L >> 1) & 1) ? qzh[gb + 1] : -qzh[gb + 1];
                pht += (L & 1)        ? qzh[gb + 0] : -qzh[gb + 0];
                const float z13 = qzh[gb + 13];
                const float a0 = pht - z13, a1 = pht + z13;
                const u64 Er = pk2(cosf(a0), cosf(a1));
                const u64 Ei = pk2(sinf(a0), sinf(a1));
                #pragma unroll
                for (int j = 0; j < 8; j++) {
                    const float ejr = ejt[j].x, eji = ejt[j].y;
                    const u64 EJR  = pk2(ejr,  ejr);
                    const u64 EJRn = pk2(-ejr, -ejr);
                    const u64 EJIp = pk2(eji,  eji);
                    const u64 EJIn = pk2(-eji, -eji);
                    u64 Pr  = fma2(EJR,  Er, mul2(EJIn, Ei));  //  ejr*Er - eji*Ei
                    u64 Pi  = fma2(EJR,  Ei, mul2(EJIp, Er));  //  ejr*Ei + eji*Er
                    u64 Pin = fma2(EJRn, Ei, mul2(EJIn, Er));  // -(Pi)
                    u64 nx = fma2(PX[j], Pr, mul2(PY[j], Pin));
                    u64 ny = fma2(PY[j], Pr, mul2(PX[j], Pi));
                    PX[j] = nx; PY[j] = ny;
                }
                #pragma unroll
                for (int j = 0; j < 8; j++) {
                    int p = baseC | (j << 7);
                    SX[phys64(p)] = PX[j]; SY[phys64(p)] = PY[j];
                }
                __syncthreads();             // RAW for next layer's gather
            } else {
                // Last layer: diagonal is a pure phase -> skip.
                // Expectation: g(i) = sum_w (+/-) c_w with same bit mapping.
                float gt = 0.0f;
                gt += ((L >> 3) & 1) ? -csh[12] : csh[12];
                gt += ((L >> 4) & 1) ? -csh[11] : csh[11];
                #pragma unroll
                for (int t = 0; t < 5; t++)
                    gt += ((wrp >> t) & 1) ? -csh[10 - t] : csh[10 - t];
                gt += ((L >> 2) & 1) ? -csh[2] : csh[2];
                gt += ((L >> 1) & 1) ? -csh[1] : csh[1];
                gt += (L & 1)        ? -csh[0] : csh[0];
                const float c13 = csh[13];
                #pragma unroll
                for (int j = 0; j < 8; j++) {
                    float gj = 0.0f;
                    #pragma unroll
                    for (int t = 0; t < 3; t++)
                        gj += ((j >> t) & 1) ? -csh[5 - t] : csh[5 - t];
                    float x0, x1, y0, y1;
                    upk2(PX[j], x0, x1); upk2(PY[j], y0, y1);
                    local += (x0 * x0 + y0 * y0) * (gt + gj + c13)
                           + (x1 * x1 + y1 * y1) * (gt + gj - c13);
                }
            }
        }
    }

    // deterministic reduction
    #pragma unroll
    for (int off = 16; off; off >>= 1)
        local += __shfl_down_sync(0xffffffffu, local, off);
    if (L == 0) wsum[wrp] = local;
    __syncthreads();
    if (tid == 0) {
        float tot = 0.0f;
        #pragma unroll
        for (int i = 0; i < THREADS / 32; i++) tot += wsum[i];
        // PLANAR complex output: out[0..B) = real (f1), out[B..2B) = imag (f2)
        out[circ * B + b] = tot;
    }
}

extern "C" void kernel_launch(void* const* d_in, const int* in_sizes, int n_in,
                              void* d_out, int out_size)
{
    const float *x, *qx1, *qz1, *c1, *qx2, *qz2, *c2;

    if (n_in >= 7 && in_sizes[0] > 1000) {
        // dict order: x, q_x1, q_z1, c1, q_x2, q_z2, c2
        x   = (const float*)d_in[0];
        qx1 = (const float*)d_in[1];
        qz1 = (const float*)d_in[2];
        c1  = (const float*)d_in[3];
        qx2 = (const float*)d_in[4];
        qz2 = (const float*)d_in[5];
        c2  = (const float*)d_in[6];
    } else if (n_in >= 7 && in_sizes[0] == NQ && in_sizes[1] == NQ) {
        c1  = (const float*)d_in[0];
        c2  = (const float*)d_in[1];
        qx1 = (const float*)d_in[2];
        qx2 = (const float*)d_in[3];
        qz1 = (const float*)d_in[4];
        qz2 = (const float*)d_in[5];
        x   = (const float*)d_in[6];
    } else {
        const float* qs[4] = {0, 0, 0, 0};
        const float* cs[2] = {0, 0};
        const float* xp = 0;
        int nq = 0, nc = 0;
        for (int i = 0; i < n_in; i++) {
            if (in_sizes[i] > 1000)         xp = (const float*)d_in[i];
            else if (in_sizes[i] == NGATES) { if (nq < 4) qs[nq++] = (const float*)d_in[i]; }
            else if (in_sizes[i] == NQ)     { if (nc < 2) cs[nc++] = (const float*)d_in[i]; }
        }
        x = xp; qx1 = qs[0]; qz1 = qs[1]; qx2 = qs[2]; qz2 = qs[3];
        c1 = cs[0]; c2 = cs[1];
    }

    int xsz = 0;
    for (int i = 0; i < n_in; i++) if (in_sizes[i] > xsz) xsz = in_sizes[i];
    const int B = xsz / NQ;  // 256

    cudaFuncSetAttribute(pqc_kernel,
                         cudaFuncAttributeMaxDynamicSharedMemorySize,
                         DIM * sizeof(u64));   // 128 KB (2 planes of HALF u64)

    dim3 grid(B, 2);
    pqc_kernel<<<grid, THREADS, DIM * sizeof(u64)>>>(
        x, qx1, qz1, c1, qx2, qz2, c2, (float*)d_out, B);
}

// round 12
// speedup vs baseline: 1.2385x; 1.2385x over previous
#include <cuda_runtime.h>

#define NQ      14
#define DIM     (1 << NQ)       // 16384 amplitudes
#define HALF    (DIM / 2)       // 8192 packed u64 per plane
#define NL      8
#define NGATES  ((NL + 1) * NQ) // 126 single-qubit gates
#define THREADS 512

typedef unsigned long long u64;

// XOR swizzle on u64-plane index; all passes use the same mapping.
__device__ __forceinline__ int phys64(int p) { return p ^ ((p >> 4) & 15); }

__device__ __forceinline__ u64 pk2(float lo, float hi) {
    u64 r; asm("mov.b64 %0, {%1,%2};" : "=l"(r) : "f"(lo), "f"(hi)); return r;
}
__device__ __forceinline__ void upk2(u64 v, float& lo, float& hi) {
    asm("mov.b64 {%0,%1}, %2;" : "=f"(lo), "=f"(hi) : "l"(v));
}
__device__ __forceinline__ u64 swap2(u64 v) {
    float lo, hi; upk2(v, lo, hi); return pk2(hi, lo);
}
__device__ __forceinline__ u64 fma2(u64 a, u64 b, u64 c) {
    u64 d; asm("fma.rn.f32x2 %0, %1, %2, %3;" : "=l"(d) : "l"(a), "l"(b), "l"(c));
    return d;
}
__device__ __forceinline__ u64 mul2(u64 a, u64 b) {
    u64 d; asm("mul.rn.f32x2 %0, %1, %2;" : "=l"(d) : "l"(a), "l"(b));
    return d;
}

// ---- Rx butterflies (real coefficients c = cos(qx/2), s = sin(qx/2))
// new0: x = c*x0 + s*y1 ; y = c*y0 - s*x1
// new1: x = c*x1 + s*y0 ; y = c*y1 - s*x0

// Broadcast: partners are distinct packed elements (bit BIT of j, 16 elems).
template<int BIT>
__device__ __forceinline__ void rx_bcast(u64* PX, u64* PY, float2 g) {
    const u64 C  = pk2(g.x,  g.x);
    const u64 Sp = pk2(g.y,  g.y);
    const u64 Sn = pk2(-g.y, -g.y);
    #pragma unroll
    for (int j = 0; j < 16; j++) {
        if (j & (1 << BIT)) continue;
        const int j2 = j | (1 << BIT);
        u64 x0 = PX[j], y0 = PY[j], x1 = PX[j2], y1 = PY[j2];
        PX[j]  = fma2(C, x0, mul2(Sp, y1));
        PY[j]  = fma2(C, y0, mul2(Sn, x1));
        PX[j2] = fma2(C, x1, mul2(Sp, y0));
        PY[j2] = fma2(C, y1, mul2(Sn, x0));
    }
}

// Pair-form: partners are the two lanes of each packed element.
__device__ __forceinline__ void rx_pair(u64* PX, u64* PY, float2 g) {
    const u64 C  = pk2(g.x,  g.x);
    const u64 Sp = pk2(g.y,  g.y);
    const u64 Sn = pk2(-g.y, -g.y);
    #pragma unroll
    for (int j = 0; j < 16; j++) {
        u64 px = PX[j], py = PY[j];
        u64 sxw = swap2(px), syw = swap2(py);
        PX[j] = fma2(C, px, mul2(Sp, syw));
        PY[j] = fma2(C, py, mul2(Sn, sxw));
    }
}

// Shuffle-form: partners in lane (lane ^ mask); symmetric both sides:
// x' = c*x + s*y_partner ; y' = c*y - s*x_partner.
__device__ __forceinline__ void rx_shfl(u64* PX, u64* PY, float2 g, int mask) {
    const u64 C  = pk2(g.x,  g.x);
    const u64 Sp = pk2(g.y,  g.y);
    const u64 Sn = pk2(-g.y, -g.y);
    #pragma unroll
    for (int j = 0; j < 16; j++) {
        u64 xp = __shfl_xor_sync(0xffffffffu, PX[j], mask);
        u64 yp = __shfl_xor_sync(0xffffffffu, PY[j], mask);
        PX[j] = fma2(C, PX[j], mul2(Sp, yp));
        PY[j] = fma2(C, PY[j], mul2(Sn, xp));
    }
}

// One CTA = one (batch, circuit) pair; 512 threads, 16 packed pairs each.
// Layer: A (w13 pair + w12..9 bcast, Gray-fused gather),
//        B (w8..5 bcast + w4 shfl, u64 in-place),
//        C (w3..0 bcast + merged Rz diagonal, in-place).
// Barriers: A-WAR (full), A->B (syncwarp: provably intra-warp), post-B RAW
// (full), post-C RAW (full). B and C are store-where-you-read per thread.
__global__ void __launch_bounds__(THREADS, 1)
pqc_kernel(const float* __restrict__ x,
           const float* __restrict__ qx1, const float* __restrict__ qz1,
           const float* __restrict__ c1,
           const float* __restrict__ qx2, const float* __restrict__ qz2,
           const float* __restrict__ c2,
           float* __restrict__ out, int B)
{
    extern __shared__ u64 dsm[];            // 2 * HALF u64 = 128 KB
    u64* SX = dsm;
    u64* SY = dsm + HALF;
    __shared__ float2 U2[NGATES];           // (cos(qx/2), sin(qx/2))
    __shared__ float  qzh[NGATES];          // qz/2
    __shared__ float2 ejt[16];              // per-layer j-part phase table
    __shared__ float  csh[NQ];
    __shared__ float  amp[NQ][2];
    __shared__ float  wsum[THREADS / 32];

    const int tid  = threadIdx.x;
    const int b    = blockIdx.x;
    const int circ = blockIdx.y;

    const float* qx = circ ? qx2 : qx1;
    const float* qz = circ ? qz2 : qz1;
    const float* cc = circ ? c2  : c1;

    if (tid < NGATES) {
        float ax = 0.5f * qx[tid];
        U2[tid]  = make_float2(cosf(ax), sinf(ax));   // precise (one-time)
        qzh[tid] = 0.5f * qz[tid];
    }
    if (tid < NQ) {
        csh[tid] = cc[tid];
        float bit = (x[b * NQ + tid] > 0.0f) ? 1.0f : 0.0f;
        float th = 1.5707963705062866f * bit;    // 0.5f * float32(pi) * bit
        amp[tid][0] = cosf(th);
        amp[tid][1] = sinf(th);
    }
    __syncthreads();

    u64 PX[16], PY[16];
    float local = 0.0f;

    for (int l = 0; l <= NL; l++) {
        const int gb = l * NQ;

        // ===== Pass A: i = (tid<<5)|(j<<1)|pb. pb=w13; j bits 0..3 -> w12..w9
        if (l == 0) {
            float ph = 1.0f;
            #pragma unroll
            for (int w = 0; w < 9; w++)
                ph *= amp[w][(tid >> (8 - w)) & 1];
            const float a13_0 = amp[13][0], a13_1 = amp[13][1];
            #pragma unroll
            for (int j = 0; j < 16; j++) {
                float pj = ph;
                #pragma unroll
                for (int w = 9; w < 13; w++)
                    pj *= amp[w][(j >> (12 - w)) & 1];
                PX[j] = pk2(pj * a13_0, pj * a13_1);
                PY[j] = 0ULL;
            }
        } else {
            // Gray gather: pair slot m <- slot m^(m>>1), lane-swap if odd src
            #pragma unroll
            for (int j = 0; j < 16; j++) {
                int m  = (tid << 4) | j;
                int ps = m ^ (m >> 1);
                u64 vx = SX[phys64(ps)], vy = SY[phys64(ps)];
                if (j & 1) { vx = swap2(vx); vy = swap2(vy); }
                PX[j] = vx; PY[j] = vy;
            }
        }
        rx_pair(PX, PY, U2[gb + 13]);
        rx_bcast<0>(PX, PY, U2[gb + 12]);
        rx_bcast<1>(PX, PY, U2[gb + 11]);
        rx_bcast<2>(PX, PY, U2[gb + 10]);
        rx_bcast<3>(PX, PY, U2[gb + 9]);
        if (l > 0) __syncthreads();          // WAR: all gathers read first
        #pragma unroll
        for (int j = 0; j < 16; j++) {
            int m = (tid << 4) | j;
            SX[phys64(m)] = PX[j]; SY[phys64(m)] = PY[j];
        }
        // A->B exchange is provably intra-warp:
        // B thread (thi<<4)|tlo reads slots written by A threads (thi<<4)|j,
        // both in warp thi>>1.
        __syncwarp();

        // ===== Pass B: p = (thi<<8)|(j<<4)|tlo; j bits -> w8..w5; w4 = shfl16
        {
            const int thi = tid >> 4, tlo = tid & 15;
            const int pbase = (thi << 8) | tlo;
            #pragma unroll
            for (int j = 0; j < 16; j++) {
                int p = pbase | (j << 4);
                PX[j] = SX[phys64(p)]; PY[j] = SY[phys64(p)];
            }
            rx_bcast<0>(PX, PY, U2[gb + 8]);
            rx_bcast<1>(PX, PY, U2[gb + 7]);
            rx_bcast<2>(PX, PY, U2[gb + 6]);
            rx_bcast<3>(PX, PY, U2[gb + 5]);
            rx_shfl(PX, PY, U2[gb + 4], 16);  // wire 4 <-> lane bit 4 (p bit 8)
            // store-where-you-read: same per-thread slots, no WAR sync needed
            #pragma unroll
            for (int j = 0; j < 16; j++) {
                int p = pbase | (j << 4);
                SX[phys64(p)] = PX[j]; SY[phys64(p)] = PY[j];
            }
            // per-layer j-part phase table (pass-C j bit t <-> wire 3-t)
            if (l < NL && tid < 16) {
                float a = 0.0f;
                #pragma unroll
                for (int w = 0; w < 4; w++)
                    a += ((tid >> (3 - w)) & 1) ? qzh[gb + w] : -qzh[gb + w];
                ejt[tid] = make_float2(__cosf(a), __sinf(a));
            }
            __syncthreads();                 // RAW for pass C (state + table)
        }

        // ===== Pass C: p = (j<<9)|tid; j bits -> w3..w0; in-place =====
        {
            #pragma unroll
            for (int j = 0; j < 16; j++) {
                int p = (j << 9) | tid;
                PX[j] = SX[phys64(p)]; PY[j] = SY[phys64(p)];
            }
            rx_bcast<0>(PX, PY, U2[gb + 3]);
            rx_bcast<1>(PX, PY, U2[gb + 2]);
            rx_bcast<2>(PX, PY, U2[gb + 1]);
            rx_bcast<3>(PX, PY, U2[gb + 0]);

            if (l < NL) {
                // Merged Rz diagonal, split into lane part E then j part ejt.
                // i = (j<<10)|(tid<<1)|lane13: tid bits 8..0 <-> wires 4..12.
                float pht = 0.0f;
                #pragma unroll
                for (int w = 4; w < 13; w++)
                    pht += ((tid >> (12 - w)) & 1) ? qzh[gb + w] : -qzh[gb + w];
                const float z13 = qzh[gb + 13];
                const float a0 = pht - z13, a1 = pht + z13;
                const float c0 = __cosf(a0), c1 = __cosf(a1);
                const float s0 = __sinf(a0), s1 = __sinf(a1);
                const u64 Er  = pk2(c0, c1);
                const u64 Eip = pk2(s0, s1);
                const u64 Ein = pk2(-s0, -s1);
                #pragma unroll
                for (int j = 0; j < 16; j++) {
                    // apply E (lane-dependent phase)
                    u64 nx = fma2(PX[j], Er, mul2(PY[j], Ein));
                    u64 ny = fma2(PY[j], Er, mul2(PX[j], Eip));
                    // apply ejt[j] (j-dependent phase)
                    const float ejr = ejt[j].x, eji = ejt[j].y;
                    const u64 EJR  = pk2(ejr,  ejr);
                    const u64 EJIp = pk2(eji,  eji);
                    const u64 EJIn = pk2(-eji, -eji);
                    PX[j] = fma2(nx, EJR, mul2(ny, EJIn));
                    PY[j] = fma2(ny, EJR, mul2(nx, EJIp));
                }
                #pragma unroll
                for (int j = 0; j < 16; j++) {
                    int p = (j << 9) | tid;
                    SX[phys64(p)] = PX[j]; SY[phys64(p)] = PY[j];
                }
                __syncthreads();             // RAW for next layer's gather
            } else {
                // Last layer: diagonal is a pure phase -> skip.
                // Expectation. i = (j<<10)|(tid<<1)|lane13.
                float gt = 0.0f;
                #pragma unroll
                for (int w = 4; w < 13; w++)
                    gt += ((tid >> (12 - w)) & 1) ? -csh[w] : csh[w];
                const float c13 = csh[13];
                #pragma unroll
                for (int j = 0; j < 16; j++) {
                    float gj = 0.0f;
                    #pragma unroll
                    for (int w = 0; w < 4; w++)
                        gj += ((j >> (3 - w)) & 1) ? -csh[w] : csh[w];
                    float x0, x1, y0, y1;
                    upk2(PX[j], x0, x1); upk2(PY[j], y0, y1);
                    local += (x0 * x0 + y0 * y0) * (gt + gj + c13)
                           + (x1 * x1 + y1 * y1) * (gt + gj - c13);
                }
            }
        }
    }

    // deterministic reduction
    #pragma unroll
    for (int off = 16; off; off >>= 1)
        local += __shfl_down_sync(0xffffffffu, local, off);
    if ((tid & 31) == 0) wsum[tid >> 5] = local;
    __syncthreads();
    if (tid == 0) {
        float tot = 0.0f;
        #pragma unroll
        for (int i = 0; i < THREADS / 32; i++) tot += wsum[i];
        // PLANAR complex output: out[0..B) = real (f1), out[B..2B) = imag (f2)
        out[circ * B + b] = tot;
    }
}

extern "C" void kernel_launch(void* const* d_in, const int* in_sizes, int n_in,
                              void* d_out, int out_size)
{
    const float *x, *qx1, *qz1, *c1, *qx2, *qz2, *c2;

    if (n_in >= 7 && in_sizes[0] > 1000) {
        // dict order: x, q_x1, q_z1, c1, q_x2, q_z2, c2
        x   = (const float*)d_in[0];
        qx1 = (const float*)d_in[1];
        qz1 = (const float*)d_in[2];
        c1  = (const float*)d_in[3];
        qx2 = (const float*)d_in[4];
        qz2 = (const float*)d_in[5];
        c2  = (const float*)d_in[6];
    } else if (n_in >= 7 && in_sizes[0] == NQ && in_sizes[1] == NQ) {
        c1  = (const float*)d_in[0];
        c2  = (const float*)d_in[1];
        qx1 = (const float*)d_in[2];
        qx2 = (const float*)d_in[3];
        qz1 = (const float*)d_in[4];
        qz2 = (const float*)d_in[5];
        x   = (const float*)d_in[6];
    } else {
        const float* qs[4] = {0, 0, 0, 0};
        const float* cs[2] = {0, 0};
        const float* xp = 0;
        int nq = 0, nc = 0;
        for (int i = 0; i < n_in; i++) {
            if (in_sizes[i] > 1000)         xp = (const float*)d_in[i];
            else if (in_sizes[i] == NGATES) { if (nq < 4) qs[nq++] = (const float*)d_in[i]; }
            else if (in_sizes[i] == NQ)     { if (nc < 2) cs[nc++] = (const float*)d_in[i]; }
        }
        x = xp; qx1 = qs[0]; qz1 = qs[1]; qx2 = qs[2]; qz2 = qs[3];
        c1 = cs[0]; c2 = cs[1];
    }

    int xsz = 0;
    for (int i = 0; i < n_in; i++) if (in_sizes[i] > xsz) xsz = in_sizes[i];
    const int B = xsz / NQ;  // 256

    cudaFuncSetAttribute(pqc_kernel,
                         cudaFuncAttributeMaxDynamicSharedMemorySize,
                         DIM * sizeof(u64));   // 128 KB (2 planes of HALF u64)

    dim3 grid(B, 2);
    pqc_kernel<<<grid, THREADS, DIM * sizeof(u64)>>>(
        x, qx1, qz1, c1, qx2, qz2, c2, (float*)d_out, B);
}

// round 13
// speedup vs baseline: 1.3062x; 1.0547x over previous
#include <cuda_runtime.h>

#define NQ      14
#define DIM     (1 << NQ)       // 16384 amplitudes
#define HALF    (DIM / 2)       // 8192 packed (x,y) u64-pair slots
#define NL      8
#define NGATES  ((NL + 1) * NQ) // 126 single-qubit gates
#define THREADS 512

typedef unsigned long long u64;

// XOR swizzle on slot index; all passes use the same mapping.
__device__ __forceinline__ int phys64(int p) { return p ^ ((p >> 4) & 15); }

__device__ __forceinline__ u64 pk2(float lo, float hi) {
    u64 r; asm("mov.b64 %0, {%1,%2};" : "=l"(r) : "f"(lo), "f"(hi)); return r;
}
__device__ __forceinline__ void upk2(u64 v, float& lo, float& hi) {
    asm("mov.b64 {%0,%1}, %2;" : "=f"(lo), "=f"(hi) : "l"(v));
}
__device__ __forceinline__ u64 swap2(u64 v) {
    float lo, hi; upk2(v, lo, hi); return pk2(hi, lo);
}
__device__ __forceinline__ u64 fma2(u64 a, u64 b, u64 c) {
    u64 d; asm("fma.rn.f32x2 %0, %1, %2, %3;" : "=l"(d) : "l"(a), "l"(b), "l"(c));
    return d;
}
__device__ __forceinline__ u64 mul2(u64 a, u64 b) {
    u64 d; asm("mul.rn.f32x2 %0, %1, %2;" : "=l"(d) : "l"(a), "l"(b));
    return d;
}

// ---- Rx butterflies (real coefficients c = cos(qx/2), s = sin(qx/2))
// new0: x = c*x0 + s*y1 ; y = c*y0 - s*x1
// new1: x = c*x1 + s*y0 ; y = c*y1 - s*x0

// Broadcast: partners are distinct packed elements (bit BIT of j, 16 elems).
template<int BIT>
__device__ __forceinline__ void rx_bcast(u64* PX, u64* PY, float2 g) {
    const u64 C  = pk2(g.x,  g.x);
    const u64 Sp = pk2(g.y,  g.y);
    const u64 Sn = pk2(-g.y, -g.y);
    #pragma unroll
    for (int j = 0; j < 16; j++) {
        if (j & (1 << BIT)) continue;
        const int j2 = j | (1 << BIT);
        u64 x0 = PX[j], y0 = PY[j], x1 = PX[j2], y1 = PY[j2];
        PX[j]  = fma2(C, x0, mul2(Sp, y1));
        PY[j]  = fma2(C, y0, mul2(Sn, x1));
        PX[j2] = fma2(C, x1, mul2(Sp, y0));
        PY[j2] = fma2(C, y1, mul2(Sn, x0));
    }
}

// Pair-form: partners are the two lanes of each packed element.
__device__ __forceinline__ void rx_pair(u64* PX, u64* PY, float2 g) {
    const u64 C  = pk2(g.x,  g.x);
    const u64 Sp = pk2(g.y,  g.y);
    const u64 Sn = pk2(-g.y, -g.y);
    #pragma unroll
    for (int j = 0; j < 16; j++) {
        u64 px = PX[j], py = PY[j];
        u64 sxw = swap2(px), syw = swap2(py);
        PX[j] = fma2(C, px, mul2(Sp, syw));
        PY[j] = fma2(C, py, mul2(Sn, sxw));
    }
}

// Shuffle-form: partners in lane (lane ^ mask); symmetric both sides:
// x' = c*x + s*y_partner ; y' = c*y - s*x_partner.
__device__ __forceinline__ void rx_shfl(u64* PX, u64* PY, float2 g, int mask) {
    const u64 C  = pk2(g.x,  g.x);
    const u64 Sp = pk2(g.y,  g.y);
    const u64 Sn = pk2(-g.y, -g.y);
    #pragma unroll
    for (int j = 0; j < 16; j++) {
        u64 xp = __shfl_xor_sync(0xffffffffu, PX[j], mask);
        u64 yp = __shfl_xor_sync(0xffffffffu, PY[j], mask);
        PX[j] = fma2(C, PX[j], mul2(Sp, yp));
        PY[j] = fma2(C, PY[j], mul2(Sn, xp));
    }
}

// One CTA = one (batch, circuit) pair; 512 threads, 16 packed pairs each.
// State: ONE interleaved SMEM plane of ulonglong2 slots (x-pair, y-pair) so
// every element moves as a single LDS.128/STS.128.
// Layer: A (w13 pair + w12..9 bcast, Gray-fused gather),
//        B (w8..5 bcast + w4 shfl, in-place),
//        C (w3..0 bcast + merged Rz diagonal, in-place).
__global__ void __launch_bounds__(THREADS, 1)
pqc_kernel(const float* __restrict__ x,
           const float* __restrict__ qx1, const float* __restrict__ qz1,
           const float* __restrict__ c1,
           const float* __restrict__ qx2, const float* __restrict__ qz2,
           const float* __restrict__ c2,
           float* __restrict__ out, int B)
{
    extern __shared__ ulonglong2 SP[];      // HALF slots = 128 KB
    __shared__ float2 U2[NGATES];           // (cos(qx/2), sin(qx/2))
    __shared__ float  qzh[NGATES];          // qz/2
    __shared__ float2 ejt[16];              // per-layer j-part phase table
    __shared__ float  csh[NQ];
    __shared__ float  amp[NQ][2];
    __shared__ float  wsum[THREADS / 32];

    const int tid  = threadIdx.x;
    const int b    = blockIdx.x;
    const int circ = blockIdx.y;

    const float* qx = circ ? qx2 : qx1;
    const float* qz = circ ? qz2 : qz1;
    const float* cc = circ ? c2  : c1;

    if (tid < NGATES) {
        float ax = 0.5f * qx[tid];
        U2[tid]  = make_float2(cosf(ax), sinf(ax));   // precise (one-time)
        qzh[tid] = 0.5f * qz[tid];
    }
    if (tid < NQ) {
        csh[tid] = cc[tid];
        float bit = (x[b * NQ + tid] > 0.0f) ? 1.0f : 0.0f;
        float th = 1.5707963705062866f * bit;    // 0.5f * float32(pi) * bit
        amp[tid][0] = cosf(th);
        amp[tid][1] = sinf(th);
    }
    __syncthreads();

    u64 PX[16], PY[16];
    float local = 0.0f;

    for (int l = 0; l <= NL; l++) {
        const int gb = l * NQ;

        // ===== Pass A: i = (tid<<5)|(j<<1)|pb. pb=w13; j bits 0..3 -> w12..w9
        if (l == 0) {
            float ph = 1.0f;
            #pragma unroll
            for (int w = 0; w < 9; w++)
                ph *= amp[w][(tid >> (8 - w)) & 1];
            const float a13_0 = amp[13][0], a13_1 = amp[13][1];
            #pragma unroll
            for (int j = 0; j < 16; j++) {
                float pj = ph;
                #pragma unroll
                for (int w = 9; w < 13; w++)
                    pj *= amp[w][(j >> (12 - w)) & 1];
                PX[j] = pk2(pj * a13_0, pj * a13_1);
                PY[j] = 0ULL;
            }
        } else {
            // Gray gather: pair slot m <- slot m^(m>>1), lane-swap if odd src
            #pragma unroll
            for (int j = 0; j < 16; j++) {
                int m  = (tid << 4) | j;
                int ps = m ^ (m >> 1);
                ulonglong2 v = SP[phys64(ps)];
                if (j & 1) { PX[j] = swap2(v.x); PY[j] = swap2(v.y); }
                else       { PX[j] = v.x;        PY[j] = v.y; }
            }
        }
        rx_pair(PX, PY, U2[gb + 13]);
        rx_bcast<0>(PX, PY, U2[gb + 12]);
        rx_bcast<1>(PX, PY, U2[gb + 11]);
        rx_bcast<2>(PX, PY, U2[gb + 10]);
        rx_bcast<3>(PX, PY, U2[gb + 9]);
        if (l > 0) __syncthreads();          // WAR: all gathers read first
        #pragma unroll
        for (int j = 0; j < 16; j++) {
            int m = (tid << 4) | j;
            SP[phys64(m)] = make_ulonglong2(PX[j], PY[j]);
        }
        // A->B exchange is provably intra-warp:
        // B thread (thi<<4)|tlo reads slots written by A threads (thi<<4)|j,
        // both in warp thi>>1.
        __syncwarp();

        // ===== Pass B: p = (thi<<8)|(j<<4)|tlo; j bits -> w8..w5; w4 = shfl16
        {
            const int thi = tid >> 4, tlo = tid & 15;
            const int pbase = (thi << 8) | tlo;
            #pragma unroll
            for (int j = 0; j < 16; j++) {
                ulonglong2 v = SP[phys64(pbase | (j << 4))];
                PX[j] = v.x; PY[j] = v.y;
            }
            rx_bcast<0>(PX, PY, U2[gb + 8]);
            rx_bcast<1>(PX, PY, U2[gb + 7]);
            rx_bcast<2>(PX, PY, U2[gb + 6]);
            rx_bcast<3>(PX, PY, U2[gb + 5]);
            rx_shfl(PX, PY, U2[gb + 4], 16);  // wire 4 <-> lane bit 4 (p bit 8)
            // store-where-you-read: same per-thread slots, no WAR sync needed
            #pragma unroll
            for (int j = 0; j < 16; j++)
                SP[phys64(pbase | (j << 4))] = make_ulonglong2(PX[j], PY[j]);
            // per-layer j-part phase table (pass-C j bit t <-> wire 3-t)
            if (l < NL && tid < 16) {
                float a = 0.0f;
                #pragma unroll
                for (int w = 0; w < 4; w++)
                    a += ((tid >> (3 - w)) & 1) ? qzh[gb + w] : -qzh[gb + w];
                ejt[tid] = make_float2(__cosf(a), __sinf(a));
            }
            __syncthreads();                 // RAW for pass C (state + table)
        }

        // ===== Pass C: p = (j<<9)|tid; j bits -> w3..w0; in-place =====
        {
            #pragma unroll
            for (int j = 0; j < 16; j++) {
                ulonglong2 v = SP[phys64((j << 9) | tid)];
                PX[j] = v.x; PY[j] = v.y;
            }
            rx_bcast<0>(PX, PY, U2[gb + 3]);
            rx_bcast<1>(PX, PY, U2[gb + 2]);
            rx_bcast<2>(PX, PY, U2[gb + 1]);
            rx_bcast<3>(PX, PY, U2[gb + 0]);

            if (l < NL) {
                // Merged Rz diagonal, split into lane part E then j part ejt.
                // i = (j<<10)|(tid<<1)|lane13: tid bits 8..0 <-> wires 4..12.
                float pht = 0.0f;
                #pragma unroll
                for (int w = 4; w < 13; w++)
                    pht += ((tid >> (12 - w)) & 1) ? qzh[gb + w] : -qzh[gb + w];
                const float z13 = qzh[gb + 13];
                const float a0 = pht - z13, a1 = pht + z13;
                const float c0 = __cosf(a0), c1 = __cosf(a1);
                const float s0 = __sinf(a0), s1 = __sinf(a1);
                const u64 Er  = pk2(c0, c1);
                const u64 Eip = pk2(s0, s1);
                const u64 Ein = pk2(-s0, -s1);
                #pragma unroll
                for (int j = 0; j < 16; j++) {
                    // apply E (lane-dependent phase)
                    u64 nx = fma2(PX[j], Er, mul2(PY[j], Ein));
                    u64 ny = fma2(PY[j], Er, mul2(PX[j], Eip));
                    // apply ejt[j] (j-dependent phase)
                    const float ejr = ejt[j].x, eji = ejt[j].y;
                    const u64 EJR  = pk2(ejr,  ejr);
                    const u64 EJIp = pk2(eji,  eji);
                    const u64 EJIn = pk2(-eji, -eji);
                    PX[j] = fma2(nx, EJR, mul2(ny, EJIn));
                    PY[j] = fma2(ny, EJR, mul2(nx, EJIp));
                }
                #pragma unroll
                for (int j = 0; j < 16; j++)
                    SP[phys64((j << 9) | tid)] = make_ulonglong2(PX[j], PY[j]);
                __syncthreads();             // RAW for next layer's gather
            } else {
                // Last layer: diagonal is a pure phase -> skip.
                // Expectation. i = (j<<10)|(tid<<1)|lane13.
                float gt = 0.0f;
                #pragma unroll
                for (int w = 4; w < 13; w++)
                    gt += ((tid >> (12 - w)) & 1) ? -csh[w] : csh[w];
                const float c13 = csh[13];
                #pragma unroll
                for (int j = 0; j < 16; j++) {
                    float gj = 0.0f;
                    #pragma unroll
                    for (int w = 0; w < 4; w++)
                        gj += ((j >> (3 - w)) & 1) ? -csh[w] : csh[w];
                    float x0, x1, y0, y1;
                    upk2(PX[j], x0, x1); upk2(PY[j], y0, y1);
                    local += (x0 * x0 + y0 * y0) * (gt + gj + c13)
                           + (x1 * x1 + y1 * y1) * (gt + gj - c13);
                }
            }
        }
    }

    // deterministic reduction
    #pragma unroll
    for (int off = 16; off; off >>= 1)
        local += __shfl_down_sync(0xffffffffu, local, off);
    if ((tid & 31) == 0) wsum[tid >> 5] = local;
    __syncthreads();
    if (tid == 0) {
        float tot = 0.0f;
        #pragma unroll
        for (int i = 0; i < THREADS / 32; i++) tot += wsum[i];
        // PLANAR complex output: out[0..B) = real (f1), out[B..2B) = imag (f2)
        out[circ * B + b] = tot;
    }
}

extern "C" void kernel_launch(void* const* d_in, const int* in_sizes, int n_in,
                              void* d_out, int out_size)
{
    const float *x, *qx1, *qz1, *c1, *qx2, *qz2, *c2;

    if (n_in >= 7 && in_sizes[0] > 1000) {
        // dict order: x, q_x1, q_z1, c1, q_x2, q_z2, c2
        x   = (const float*)d_in[0];
        qx1 = (const float*)d_in[1];
        qz1 = (const float*)d_in[2];
        c1  = (const float*)d_in[3];
        qx2 = (const float*)d_in[4];
        qz2 = (const float*)d_in[5];
        c2  = (const float*)d_in[6];
    } else if (n_in >= 7 && in_sizes[0] == NQ && in_sizes[1] == NQ) {
        c1  = (const float*)d_in[0];
        c2  = (const float*)d_in[1];
        qx1 = (const float*)d_in[2];
        qx2 = (const float*)d_in[3];
        qz1 = (const float*)d_in[4];
        qz2 = (const float*)d_in[5];
        x   = (const float*)d_in[6];
    } else {
        const float* qs[4] = {0, 0, 0, 0};
        const float* cs[2] = {0, 0};
        const float* xp = 0;
        int nq = 0, nc = 0;
        for (int i = 0; i < n_in; i++) {
            if (in_sizes[i] > 1000)         xp = (const float*)d_in[i];
            else if (in_sizes[i] == NGATES) { if (nq < 4) qs[nq++] = (const float*)d_in[i]; }
            else if (in_sizes[i] == NQ)     { if (nc < 2) cs[nc++] = (const float*)d_in[i]; }
        }
        x = xp; qx1 = qs[0]; qz1 = qs[1]; qx2 = qs[2]; qz2 = qs[3];
        c1 = cs[0]; c2 = cs[1];
    }

    int xsz = 0;
    for (int i = 0; i < n_in; i++) if (in_sizes[i] > xsz) xsz = in_sizes[i];
    const int B = xsz / NQ;  // 256

    cudaFuncSetAttribute(pqc_kernel,
                         cudaFuncAttributeMaxDynamicSharedMemorySize,
                         HALF * sizeof(ulonglong2));   // 128 KB interleaved

    dim3 grid(B, 2);
    pqc_kernel<<<grid, THREADS, HALF * sizeof(ulonglong2)>>>(
        x, qx1, qz1, c1, qx2, qz2, c2, (float*)d_out, B);
}

// round 14
// speedup vs baseline: 1.3817x; 1.0578x over previous
#include <cuda_runtime.h>

#define NQ      14
#define DIM     (1 << NQ)       // 16384 amplitudes
#define HALF    (DIM / 2)       // 8192 packed (x,y) u64-pair slots
#define NL      8
#define NGATES  ((NL + 1) * NQ) // 126 single-qubit gates
#define THREADS 512

typedef unsigned long long u64;

// XOR swizzle on slot index; all passes use the same mapping.
__device__ __forceinline__ int phys64(int p) { return p ^ ((p >> 4) & 15); }

__device__ __forceinline__ u64 pk2(float lo, float hi) {
    u64 r; asm("mov.b64 %0, {%1,%2};" : "=l"(r) : "f"(lo), "f"(hi)); return r;
}
__device__ __forceinline__ void upk2(u64 v, float& lo, float& hi) {
    asm("mov.b64 {%0,%1}, %2;" : "=f"(lo), "=f"(hi) : "l"(v));
}
__device__ __forceinline__ u64 swap2(u64 v) {
    float lo, hi; upk2(v, lo, hi); return pk2(hi, lo);
}
__device__ __forceinline__ u64 fma2(u64 a, u64 b, u64 c) {
    u64 d; asm("fma.rn.f32x2 %0, %1, %2, %3;" : "=l"(d) : "l"(a), "l"(b), "l"(c));
    return d;
}
__device__ __forceinline__ u64 mul2(u64 a, u64 b) {
    u64 d; asm("mul.rn.f32x2 %0, %1, %2;" : "=l"(d) : "l"(a), "l"(b));
    return d;
}

// ---- Rx butterflies (real coefficients c = cos(qx/2), s = sin(qx/2))
// new0: x = c*x0 + s*y1 ; y = c*y0 - s*x1
// new1: x = c*x1 + s*y0 ; y = c*y1 - s*x0

// Broadcast: partners are distinct packed elements (bit BIT of j, 16 elems).
template<int BIT>
__device__ __forceinline__ void rx_bcast(u64* PX, u64* PY, float2 g) {
    const u64 C  = pk2(g.x,  g.x);
    const u64 Sp = pk2(g.y,  g.y);
    const u64 Sn = pk2(-g.y, -g.y);
    #pragma unroll
    for (int j = 0; j < 16; j++) {
        if (j & (1 << BIT)) continue;
        const int j2 = j | (1 << BIT);
        u64 x0 = PX[j], y0 = PY[j], x1 = PX[j2], y1 = PY[j2];
        PX[j]  = fma2(C, x0, mul2(Sp, y1));
        PY[j]  = fma2(C, y0, mul2(Sn, x1));
        PX[j2] = fma2(C, x1, mul2(Sp, y0));
        PY[j2] = fma2(C, y1, mul2(Sn, x0));
    }
}

// Pair-form: partners are the two lanes of each packed element.
__device__ __forceinline__ void rx_pair(u64* PX, u64* PY, float2 g) {
    const u64 C  = pk2(g.x,  g.x);
    const u64 Sp = pk2(g.y,  g.y);
    const u64 Sn = pk2(-g.y, -g.y);
    #pragma unroll
    for (int j = 0; j < 16; j++) {
        u64 px = PX[j], py = PY[j];
        u64 sxw = swap2(px), syw = swap2(py);
        PX[j] = fma2(C, px, mul2(Sp, syw));
        PY[j] = fma2(C, py, mul2(Sn, sxw));
    }
}

// Shuffle-form: partners in lane (lane ^ mask); symmetric both sides:
// x' = c*x + s*y_partner ; y' = c*y - s*x_partner.
__device__ __forceinline__ void rx_shfl(u64* PX, u64* PY, float2 g, int mask) {
    const u64 C  = pk2(g.x,  g.x);
    const u64 Sp = pk2(g.y,  g.y);
    const u64 Sn = pk2(-g.y, -g.y);
    #pragma unroll
    for (int j = 0; j < 16; j++) {
        u64 xp = __shfl_xor_sync(0xffffffffu, PX[j], mask);
        u64 yp = __shfl_xor_sync(0xffffffffu, PY[j], mask);
        PX[j] = fma2(C, PX[j], mul2(Sp, yp));
        PY[j] = fma2(C, PY[j], mul2(Sn, xp));
    }
}

// One CTA = one (batch, circuit) pair; 512 threads, 16 packed pairs each.
// LAYER 0 IS FREE: the init is a product state and layer 0 has only
// single-qubit gates before its CNOT ladder, so amp'_w = Rz0_w Rx0_w amp_w is
// folded per-wire into the init; layer 0's CNOT is layer 1's Gray gather.
// Layers 1..8: A (w13 pair + w12..9 bcast, Gray-fused gather),
//              B (w8..5 bcast + w4 shfl, in-place),
//              C (w3..0 bcast + merged Rz diagonal, in-place).
__global__ void __launch_bounds__(THREADS, 1)
pqc_kernel(const float* __restrict__ x,
           const float* __restrict__ qx1, const float* __restrict__ qz1,
           const float* __restrict__ c1,
           const float* __restrict__ qx2, const float* __restrict__ qz2,
           const float* __restrict__ c2,
           float* __restrict__ out, int B)
{
    extern __shared__ ulonglong2 SP[];      // HALF slots = 128 KB
    __shared__ float2 U2[NGATES];           // (cos(qx/2), sin(qx/2))
    __shared__ float  qzh[NGATES];          // qz/2
    __shared__ float2 ejt[16];              // per-layer j-part phase table
    __shared__ float2 a2[NQ][2];            // layer-0-transformed qubit amps
    __shared__ float2 jtab[16];             // init j-part complex products
    __shared__ float  csh[NQ];
    __shared__ float  wsum[THREADS / 32];

    const int tid  = threadIdx.x;
    const int b    = blockIdx.x;
    const int circ = blockIdx.y;

    const float* qx = circ ? qx2 : qx1;
    const float* qz = circ ? qz2 : qz1;
    const float* cc = circ ? c2  : c1;

    if (tid < NGATES) {
        float ax = 0.5f * qx[tid];
        U2[tid]  = make_float2(cosf(ax), sinf(ax));   // precise (one-time)
        qzh[tid] = 0.5f * qz[tid];
    }
    if (tid < NQ) {
        csh[tid] = cc[tid];
        // per-wire init amp (cos th, sin th), th = 0.5f*pi(f32)*bit
        float bit = (x[b * NQ + tid] > 0.0f) ? 1.0f : 0.0f;
        float th  = 1.5707963705062866f * bit;
        float a0 = cosf(th), a1 = sinf(th);
        // fold layer-0 gate U = Rz(qz0)Rx(qx0): amp' = U * (a0, a1)
        float ax = 0.5f * qx[tid];
        float az = 0.5f * qz[tid];
        float cx = cosf(ax), sx = sinf(ax);
        float pr = cosf(az), pii = -sinf(az);   // pm = (pr, pii), pp = conj
        float t0 = cx * a0, t1 = sx * a1, t2 = sx * a0, t3 = cx * a1;
        // amp'0 = pm*(t0 - i t1), amp'1 = pp*(t3 - i t2)
        a2[tid][0] = make_float2(pr * t0 + pii * t1,  pii * t0 - pr * t1);
        a2[tid][1] = make_float2(pr * t3 - pii * t2, -pii * t3 - pr * t2);
    }
    __syncthreads();

    // init j-table: products over wires 9..12 (j bit (12-w) selects)
    if (tid < 16) {
        float2 q = a2[9][(tid >> 3) & 1];
        #pragma unroll
        for (int w = 10; w < 13; w++) {
            float2 aw = a2[w][(tid >> (12 - w)) & 1];
            q = make_float2(q.x * aw.x - q.y * aw.y,
                            q.x * aw.y + q.y * aw.x);
        }
        jtab[tid] = q;
    }

    // thread-part product over wires 0..8 (tid bit (8-w))
    float2 T = a2[0][(tid >> 8) & 1];
    #pragma unroll
    for (int w = 1; w < 9; w++) {
        float2 aw = a2[w][(tid >> (8 - w)) & 1];
        T = make_float2(T.x * aw.x - T.y * aw.y,
                        T.x * aw.y + T.y * aw.x);
    }
    __syncthreads();   // jtab ready

    u64 PX[16], PY[16];
    float local = 0.0f;

    // ---- init state = layer-0 output, straight into canonical layout ----
    {
        const float a13x0 = a2[13][0].x, a13y0 = a2[13][0].y;
        const float a13x1 = a2[13][1].x, a13y1 = a2[13][1].y;
        #pragma unroll
        for (int j = 0; j < 16; j++) {
            float2 jt = jtab[j];
            float qr = T.x * jt.x - T.y * jt.y;
            float qi = T.x * jt.y + T.y * jt.x;
            PX[j] = pk2(qr * a13x0 - qi * a13y0, qr * a13x1 - qi * a13y1);
            PY[j] = pk2(qr * a13y0 + qi * a13x0, qr * a13y1 + qi * a13x1);
            SP[phys64((tid << 4) | j)] = make_ulonglong2(PX[j], PY[j]);
        }
        __syncthreads();   // RAW for layer 1's Gray gather
    }

    for (int l = 1; l <= NL; l++) {
        const int gb = l * NQ;

        // ===== Pass A: i = (tid<<5)|(j<<1)|pb. pb=w13; j bits 0..3 -> w12..w9
        // Gray gather (prev layer's CNOT ladder): slot m <- slot m^(m>>1)
        #pragma unroll
        for (int j = 0; j < 16; j++) {
            int m  = (tid << 4) | j;
            int ps = m ^ (m >> 1);
            ulonglong2 v = SP[phys64(ps)];
            if (j & 1) { PX[j] = swap2(v.x); PY[j] = swap2(v.y); }
            else       { PX[j] = v.x;        PY[j] = v.y; }
        }
        rx_pair(PX, PY, U2[gb + 13]);
        rx_bcast<0>(PX, PY, U2[gb + 12]);
        rx_bcast<1>(PX, PY, U2[gb + 11]);
        rx_bcast<2>(PX, PY, U2[gb + 10]);
        rx_bcast<3>(PX, PY, U2[gb + 9]);
        __syncthreads();                     // WAR: all gathers read first
        #pragma unroll
        for (int j = 0; j < 16; j++) {
            int m = (tid << 4) | j;
            SP[phys64(m)] = make_ulonglong2(PX[j], PY[j]);
        }
        // A->B exchange is provably intra-warp:
        // B thread (thi<<4)|tlo reads slots written by A threads (thi<<4)|j,
        // both in warp thi>>1.
        __syncwarp();

        // ===== Pass B: p = (thi<<8)|(j<<4)|tlo; j bits -> w8..w5; w4 = shfl16
        {
            const int thi = tid >> 4, tlo = tid & 15;
            const int pbase = (thi << 8) | tlo;
            #pragma unroll
            for (int j = 0; j < 16; j++) {
                ulonglong2 v = SP[phys64(pbase | (j << 4))];
                PX[j] = v.x; PY[j] = v.y;
            }
            rx_bcast<0>(PX, PY, U2[gb + 8]);
            rx_bcast<1>(PX, PY, U2[gb + 7]);
            rx_bcast<2>(PX, PY, U2[gb + 6]);
            rx_bcast<3>(PX, PY, U2[gb + 5]);
            rx_shfl(PX, PY, U2[gb + 4], 16);  // wire 4 <-> lane bit 4 (p bit 8)
            // store-where-you-read: same per-thread slots, no WAR sync needed
            #pragma unroll
            for (int j = 0; j < 16; j++)
                SP[phys64(pbase | (j << 4))] = make_ulonglong2(PX[j], PY[j]);
            // per-layer j-part phase table (pass-C j bit t <-> wire 3-t)
            if (l < NL && tid < 16) {
                float a = 0.0f;
                #pragma unroll
                for (int w = 0; w < 4; w++)
                    a += ((tid >> (3 - w)) & 1) ? qzh[gb + w] : -qzh[gb + w];
                ejt[tid] = make_float2(__cosf(a), __sinf(a));
            }
            __syncthreads();                 // RAW for pass C (state + table)
        }

        // ===== Pass C: p = (j<<9)|tid; j bits -> w3..w0; in-place =====
        {
            #pragma unroll
            for (int j = 0; j < 16; j++) {
                ulonglong2 v = SP[phys64((j << 9) | tid)];
                PX[j] = v.x; PY[j] = v.y;
            }
            rx_bcast<0>(PX, PY, U2[gb + 3]);
            rx_bcast<1>(PX, PY, U2[gb + 2]);
            rx_bcast<2>(PX, PY, U2[gb + 1]);
            rx_bcast<3>(PX, PY, U2[gb + 0]);

            if (l < NL) {
                // Merged Rz diagonal, split into lane part E then j part ejt.
                // i = (j<<10)|(tid<<1)|lane13: tid bits 8..0 <-> wires 4..12.
                float pht = 0.0f;
                #pragma unroll
                for (int w = 4; w < 13; w++)
                    pht += ((tid >> (12 - w)) & 1) ? qzh[gb + w] : -qzh[gb + w];
                const float z13 = qzh[gb + 13];
                const float aa0 = pht - z13, aa1 = pht + z13;
                const float c0 = __cosf(aa0), c1 = __cosf(aa1);
                const float s0 = __sinf(aa0), s1 = __sinf(aa1);
                const u64 Er  = pk2(c0, c1);
                const u64 Eip = pk2(s0, s1);
                const u64 Ein = pk2(-s0, -s1);
                #pragma unroll
                for (int j = 0; j < 16; j++) {
                    // apply E (lane-dependent phase)
                    u64 nx = fma2(PX[j], Er, mul2(PY[j], Ein));
                    u64 ny = fma2(PY[j], Er, mul2(PX[j], Eip));
                    // apply ejt[j] (j-dependent phase)
                    const float ejr = ejt[j].x, eji = ejt[j].y;
                    const u64 EJR  = pk2(ejr,  ejr);
                    const u64 EJIp = pk2(eji,  eji);
                    const u64 EJIn = pk2(-eji, -eji);
                    PX[j] = fma2(nx, EJR, mul2(ny, EJIn));
                    PY[j] = fma2(ny, EJR, mul2(nx, EJIp));
                }
                #pragma unroll
                for (int j = 0; j < 16; j++)
                    SP[phys64((j << 9) | tid)] = make_ulonglong2(PX[j], PY[j]);
                __syncthreads();             // RAW for next layer's gather
            } else {
                // Last layer: diagonal is a pure phase -> skip.
                // Expectation. i = (j<<10)|(tid<<1)|lane13.
                float gt = 0.0f;
                #pragma unroll
                for (int w = 4; w < 13; w++)
                    gt += ((tid >> (12 - w)) & 1) ? -csh[w] : csh[w];
                const float c13 = csh[13];
                #pragma unroll
                for (int j = 0; j < 16; j++) {
                    float gj = 0.0f;
                    #pragma unroll
                    for (int w = 0; w < 4; w++)
                        gj += ((j >> (3 - w)) & 1) ? -csh[w] : csh[w];
                    float x0, x1, y0, y1;
                    upk2(PX[j], x0, x1); upk2(PY[j], y0, y1);
                    local += (x0 * x0 + y0 * y0) * (gt + gj + c13)
                           + (x1 * x1 + y1 * y1) * (gt + gj - c13);
                }
            }
        }
    }

    // deterministic reduction
    #pragma unroll
    for (int off = 16; off; off >>= 1)
        local += __shfl_down_sync(0xffffffffu, local, off);
    if ((tid & 31) == 0) wsum[tid >> 5] = local;
    __syncthreads();
    if (tid == 0) {
        float tot = 0.0f;
        #pragma unroll
        for (int i = 0; i < THREADS / 32; i++) tot += wsum[i];
        // PLANAR complex output: out[0..B) = real (f1), out[B..2B) = imag (f2)
        out[circ * B + b] = tot;
    }
}

extern "C" void kernel_launch(void* const* d_in, const int* in_sizes, int n_in,
                              void* d_out, int out_size)
{
    const float *x, *qx1, *qz1, *c1, *qx2, *qz2, *c2;

    if (n_in >= 7 && in_sizes[0] > 1000) {
        // dict order: x, q_x1, q_z1, c1, q_x2, q_z2, c2
        x   = (const float*)d_in[0];
        qx1 = (const float*)d_in[1];
        qz1 = (const float*)d_in[2];
        c1  = (const float*)d_in[3];
        qx2 = (const float*)d_in[4];
        qz2 = (const float*)d_in[5];
        c2  = (const float*)d_in[6];
    } else if (n_in >= 7 && in_sizes[0] == NQ && in_sizes[1] == NQ) {
        c1  = (const float*)d_in[0];
        c2  = (const float*)d_in[1];
        qx1 = (const float*)d_in[2];
        qx2 = (const float*)d_in[3];
        qz1 = (const float*)d_in[4];
        qz2 = (const float*)d_in[5];
        x   = (const float*)d_in[6];
    } else {
        const float* qs[4] = {0, 0, 0, 0};
        const float* cs[2] = {0, 0};
        const float* xp = 0;
        int nq = 0, nc = 0;
        for (int i = 0; i < n_in; i++) {
            if (in_sizes[i] > 1000)         xp = (const float*)d_in[i];
            else if (in_sizes[i] == NGATES) { if (nq < 4) qs[nq++] = (const float*)d_in[i]; }
            else if (in_sizes[i] == NQ)     { if (nc < 2) cs[nc++] = (const float*)d_in[i]; }
        }
        x = xp; qx1 = qs[0]; qz1 = qs[1]; qx2 = qs[2]; qz2 = qs[3];
        c1 = cs[0]; c2 = cs[1];
    }

    int xsz = 0;
    for (int i = 0; i < n_in; i++) if (in_sizes[i] > xsz) xsz = in_sizes[i];
    const int B = xsz / NQ;  // 256

    cudaFuncSetAttribute(pqc_kernel,
                         cudaFuncAttributeMaxDynamicSharedMemorySize,
                         HALF * sizeof(ulonglong2));   // 128 KB interleaved

    dim3 grid(B, 2);
    pqc_kernel<<<grid, THREADS, HALF * sizeof(ulonglong2)>>>(
        x, qx1, qz1, c1, qx2, qz2, c2, (float*)d_out, B);
}

// round 15
// speedup vs baseline: 1.6365x; 1.1844x over previous
#include <cuda_runtime.h>

#define NQ      14
#define DIM     (1 << NQ)       // 16384 amplitudes
#define HALF    (DIM / 2)       // 8192 packed (x,y) u64-pair slots
#define NL      8
#define NGATES  ((NL + 1) * NQ) // 126 single-qubit gates
#define THREADS 512

typedef unsigned long long u64;

// XOR swizzle on slot index; all passes use the same mapping.
__device__ __forceinline__ int phys64(int p) { return p ^ ((p >> 4) & 15); }

__device__ __forceinline__ u64 pk2(float lo, float hi) {
    u64 r; asm("mov.b64 %0, {%1,%2};" : "=l"(r) : "f"(lo), "f"(hi)); return r;
}
__device__ __forceinline__ void upk2(u64 v, float& lo, float& hi) {
    asm("mov.b64 {%0,%1}, %2;" : "=f"(lo), "=f"(hi) : "l"(v));
}
__device__ __forceinline__ u64 swap2(u64 v) {
    float lo, hi; upk2(v, lo, hi); return pk2(hi, lo);
}
__device__ __forceinline__ u64 fma2(u64 a, u64 b, u64 c) {
    u64 d; asm("fma.rn.f32x2 %0, %1, %2, %3;" : "=l"(d) : "l"(a), "l"(b), "l"(c));
    return d;
}
__device__ __forceinline__ u64 mul2(u64 a, u64 b) {
    u64 d; asm("mul.rn.f32x2 %0, %1, %2;" : "=l"(d) : "l"(a), "l"(b));
    return d;
}

// ---- UNSCALED Rx butterflies with t = tan(qx/2); the dropped factor
// c = cos(qx/2) is accumulated per layer and folded into the merged Rz
// diagonal (layers 1..7) or the final expectation (layer 8).
// new0: x = x0 + t*y1 ; y = y0 - t*x1
// new1: x = x1 + t*y0 ; y = y1 - t*x0

// Broadcast: partners are distinct packed elements (bit BIT of j, 16 elems).
template<int BIT>
__device__ __forceinline__ void rx_bcast(u64* PX, u64* PY, float t) {
    const u64 Tp = pk2(t, t);
    const u64 Tn = pk2(-t, -t);
    #pragma unroll
    for (int j = 0; j < 16; j++) {
        if (j & (1 << BIT)) continue;
        const int j2 = j | (1 << BIT);
        u64 x0 = PX[j], y0 = PY[j], x1 = PX[j2], y1 = PY[j2];
        PX[j]  = fma2(Tp, y1, x0);
        PY[j]  = fma2(Tn, x1, y0);
        PX[j2] = fma2(Tp, y0, x1);
        PY[j2] = fma2(Tn, x0, y1);
    }
}

// Pair-form: partners are the two lanes of each packed element.
__device__ __forceinline__ void rx_pair(u64* PX, u64* PY, float t) {
    const u64 Tp = pk2(t, t);
    const u64 Tn = pk2(-t, -t);
    #pragma unroll
    for (int j = 0; j < 16; j++) {
        u64 sxw = swap2(PX[j]), syw = swap2(PY[j]);
        PX[j] = fma2(Tp, syw, PX[j]);   // lane0: x0 + t*y1 ; lane1: x1 + t*y0
        PY[j] = fma2(Tn, sxw, PY[j]);   // lane0: y0 - t*x1 ; lane1: y1 - t*x0
    }
}

// Shuffle-form: partners in lane (lane ^ mask); symmetric both sides.
__device__ __forceinline__ void rx_shfl(u64* PX, u64* PY, float t, int mask) {
    const u64 Tp = pk2(t, t);
    const u64 Tn = pk2(-t, -t);
    #pragma unroll
    for (int j = 0; j < 16; j++) {
        u64 xp = __shfl_xor_sync(0xffffffffu, PX[j], mask);
        u64 yp = __shfl_xor_sync(0xffffffffu, PY[j], mask);
        PX[j] = fma2(Tp, yp, PX[j]);
        PY[j] = fma2(Tn, xp, PY[j]);
    }
}

// One CTA = one (batch, circuit) pair; 512 threads, 16 packed pairs each.
// LAYER 0 IS FREE (folded into the product-state init; its CNOT is layer 1's
// Gray gather). Layers 1..8: A (w13 pair + w12..9 bcast, Gray-fused gather),
// B (w8..5 bcast + w4 shfl, in-place), C (w3..0 bcast + scaled Rz diagonal).
__global__ void __launch_bounds__(THREADS, 1)
pqc_kernel(const float* __restrict__ x,
           const float* __restrict__ qx1, const float* __restrict__ qz1,
           const float* __restrict__ c1,
           const float* __restrict__ qx2, const float* __restrict__ qz2,
           const float* __restrict__ c2,
           float* __restrict__ out, int B)
{
    extern __shared__ ulonglong2 SP[];      // HALF slots = 128 KB
    __shared__ float  tg[NGATES];           // tan(qx/2) per gate
    __shared__ float  qzh[NGATES];          // qz/2
    __shared__ float  lsc[NL + 1];          // per-layer prod of cos(qx/2)
    __shared__ float2 ejt[16];              // per-layer j-part phase table
    __shared__ float2 a2[NQ][2];            // layer-0-transformed qubit amps
    __shared__ float2 jtab[16];             // init j-part complex products
    __shared__ float  csh[NQ];
    __shared__ float  wsum[THREADS / 32];

    const int tid  = threadIdx.x;
    const int b    = blockIdx.x;
    const int circ = blockIdx.y;

    const float* qx = circ ? qx2 : qx1;
    const float* qz = circ ? qz2 : qz1;
    const float* cc = circ ? c2  : c1;

    if (tid < NGATES) {
        float ax = 0.5f * qx[tid];
        tg[tid]  = tanf(ax);                // precise (one-time); |t| <= ~0.27
        qzh[tid] = 0.5f * qz[tid];
    }
    if (tid <= NL) {                        // per-layer cos product (scale)
        float p = 1.0f;
        #pragma unroll
        for (int w = 0; w < NQ; w++)
            p *= cosf(0.5f * qx[tid * NQ + w]);
        lsc[tid] = p;
    }
    if (tid < NQ) {
        csh[tid] = cc[tid];
        // per-wire init amp (cos th, sin th), th = 0.5f*pi(f32)*bit
        float bit = (x[b * NQ + tid] > 0.0f) ? 1.0f : 0.0f;
        float th  = 1.5707963705062866f * bit;
        float a0 = cosf(th), a1 = sinf(th);
        // fold layer-0 gate U = Rz(qz0)Rx(qx0) EXACTLY (full, scaled form)
        float ax = 0.5f * qx[tid];
        float az = 0.5f * qz[tid];
        float cx = cosf(ax), sx = sinf(ax);
        float pr = cosf(az), pii = -sinf(az);   // pm = (pr, pii), pp = conj
        float t0 = cx * a0, t1 = sx * a1, t2 = sx * a0, t3 = cx * a1;
        a2[tid][0] = make_float2(pr * t0 + pii * t1,  pii * t0 - pr * t1);
        a2[tid][1] = make_float2(pr * t3 - pii * t2, -pii * t3 - pr * t2);
    }
    __syncthreads();

    // init j-table: products over wires 9..12 (j bit (12-w) selects)
    if (tid < 16) {
        float2 q = a2[9][(tid >> 3) & 1];
        #pragma unroll
        for (int w = 10; w < 13; w++) {
            float2 aw = a2[w][(tid >> (12 - w)) & 1];
            q = make_float2(q.x * aw.x - q.y * aw.y,
                            q.x * aw.y + q.y * aw.x);
        }
        jtab[tid] = q;
    }

    // thread-part product over wires 0..8 (tid bit (8-w))
    float2 T = a2[0][(tid >> 8) & 1];
    #pragma unroll
    for (int w = 1; w < 9; w++) {
        float2 aw = a2[w][(tid >> (8 - w)) & 1];
        T = make_float2(T.x * aw.x - T.y * aw.y,
                        T.x * aw.y + T.y * aw.x);
    }
    __syncthreads();   // jtab ready

    u64 PX[16], PY[16];
    float local = 0.0f;

    // ---- init state = layer-0 output, straight into canonical layout ----
    {
        const float a13x0 = a2[13][0].x, a13y0 = a2[13][0].y;
        const float a13x1 = a2[13][1].x, a13y1 = a2[13][1].y;
        #pragma unroll
        for (int j = 0; j < 16; j++) {
            float2 jt = jtab[j];
            float qr = T.x * jt.x - T.y * jt.y;
            float qi = T.x * jt.y + T.y * jt.x;
            PX[j] = pk2(qr * a13x0 - qi * a13y0, qr * a13x1 - qi * a13y1);
            PY[j] = pk2(qr * a13y0 + qi * a13x0, qr * a13y1 + qi * a13x1);
            SP[phys64((tid << 4) | j)] = make_ulonglong2(PX[j], PY[j]);
        }
        __syncthreads();   // RAW for layer 1's Gray gather
    }

    for (int l = 1; l <= NL; l++) {
        const int gb = l * NQ;

        // ===== Pass A: i = (tid<<5)|(j<<1)|pb. pb=w13; j bits 0..3 -> w12..w9
        // Gray gather (prev layer's CNOT ladder): slot m <- slot m^(m>>1)
        #pragma unroll
        for (int j = 0; j < 16; j++) {
            int m  = (tid << 4) | j;
            int ps = m ^ (m >> 1);
            ulonglong2 v = SP[phys64(ps)];
            if (j & 1) { PX[j] = swap2(v.x); PY[j] = swap2(v.y); }
            else       { PX[j] = v.x;        PY[j] = v.y; }
        }
        rx_pair(PX, PY, tg[gb + 13]);
        rx_bcast<0>(PX, PY, tg[gb + 12]);
        rx_bcast<1>(PX, PY, tg[gb + 11]);
        rx_bcast<2>(PX, PY, tg[gb + 10]);
        rx_bcast<3>(PX, PY, tg[gb + 9]);
        __syncthreads();                     // WAR: all gathers read first
        #pragma unroll
        for (int j = 0; j < 16; j++) {
            int m = (tid << 4) | j;
            SP[phys64(m)] = make_ulonglong2(PX[j], PY[j]);
        }
        // A->B exchange is provably intra-warp:
        // B thread (thi<<4)|tlo reads slots written by A threads (thi<<4)|j.
        __syncwarp();

        // ===== Pass B: p = (thi<<8)|(j<<4)|tlo; j bits -> w8..w5; w4 = shfl16
        {
            const int thi = tid >> 4, tlo = tid & 15;
            const int pbase = (thi << 8) | tlo;
            #pragma unroll
            for (int j = 0; j < 16; j++) {
                ulonglong2 v = SP[phys64(pbase | (j << 4))];
                PX[j] = v.x; PY[j] = v.y;
            }
            rx_bcast<0>(PX, PY, tg[gb + 8]);
            rx_bcast<1>(PX, PY, tg[gb + 7]);
            rx_bcast<2>(PX, PY, tg[gb + 6]);
            rx_bcast<3>(PX, PY, tg[gb + 5]);
            rx_shfl(PX, PY, tg[gb + 4], 16);  // wire 4 <-> lane bit 4 (p bit 8)
            // store-where-you-read: same per-thread slots, no WAR sync needed
            #pragma unroll
            for (int j = 0; j < 16; j++)
                SP[phys64(pbase | (j << 4))] = make_ulonglong2(PX[j], PY[j]);
            // per-layer j-part phase table (pass-C j bit t <-> wire 3-t)
            if (l < NL && tid < 16) {
                float a = 0.0f;
                #pragma unroll
                for (int w = 0; w < 4; w++)
                    a += ((tid >> (3 - w)) & 1) ? qzh[gb + w] : -qzh[gb + w];
                ejt[tid] = make_float2(__cosf(a), __sinf(a));
            }
            __syncthreads();                 // RAW for pass C (state + table)
        }

        // ===== Pass C: p = (j<<9)|tid; j bits -> w3..w0; in-place =====
        {
            #pragma unroll
            for (int j = 0; j < 16; j++) {
                ulonglong2 v = SP[phys64((j << 9) | tid)];
                PX[j] = v.x; PY[j] = v.y;
            }
            rx_bcast<0>(PX, PY, tg[gb + 3]);
            rx_bcast<1>(PX, PY, tg[gb + 2]);
            rx_bcast<2>(PX, PY, tg[gb + 1]);
            rx_bcast<3>(PX, PY, tg[gb + 0]);

            if (l < NL) {
                // Merged Rz diagonal * layer scale lsc[l] (restores the cos
                // factors dropped by the unscaled butterflies).
                // i = (j<<10)|(tid<<1)|lane13: tid bits 8..0 <-> wires 4..12.
                float pht = 0.0f;
                #pragma unroll
                for (int w = 4; w < 13; w++)
                    pht += ((tid >> (12 - w)) & 1) ? qzh[gb + w] : -qzh[gb + w];
                const float z13 = qzh[gb + 13];
                const float sc  = lsc[l];
                const float aa0 = pht - z13, aa1 = pht + z13;
                const float c0 = __cosf(aa0) * sc, c1 = __cosf(aa1) * sc;
                const float s0 = __sinf(aa0) * sc, s1 = __sinf(aa1) * sc;
                const u64 Er  = pk2(c0, c1);
                const u64 Eip = pk2(s0, s1);
                const u64 Ein = pk2(-s0, -s1);
                #pragma unroll
                for (int j = 0; j < 16; j++) {
                    // apply scaled E (lane-dependent phase)
                    u64 nx = fma2(PX[j], Er, mul2(PY[j], Ein));
                    u64 ny = fma2(PY[j], Er, mul2(PX[j], Eip));
                    // apply ejt[j] (unit-modulus j-dependent phase)
                    const float ejr = ejt[j].x, eji = ejt[j].y;
                    const u64 EJR  = pk2(ejr,  ejr);
                    const u64 EJIp = pk2(eji,  eji);
                    const u64 EJIn = pk2(-eji, -eji);
                    PX[j] = fma2(nx, EJR, mul2(ny, EJIn));
                    PY[j] = fma2(ny, EJR, mul2(nx, EJIp));
                }
                #pragma unroll
                for (int j = 0; j < 16; j++)
                    SP[phys64((j << 9) | tid)] = make_ulonglong2(PX[j], PY[j]);
                __syncthreads();             // RAW for next layer's gather
            } else {
                // Last layer: diagonal is a pure phase -> skip; the missing
                // scale lsc[NL] enters squared via the probabilities.
                // Expectation. i = (j<<10)|(tid<<1)|lane13.
                float gt = 0.0f;
                #pragma unroll
                for (int w = 4; w < 13; w++)
                    gt += ((tid >> (12 - w)) & 1) ? -csh[w] : csh[w];
                const float c13 = csh[13];
                #pragma unroll
                for (int j = 0; j < 16; j++) {
                    float gj = 0.0f;
                    #pragma unroll
                    for (int w = 0; w < 4; w++)
                        gj += ((j >> (3 - w)) & 1) ? -csh[w] : csh[w];
                    float x0, x1, y0, y1;
                    upk2(PX[j], x0, x1); upk2(PY[j], y0, y1);
                    local += (x0 * x0 + y0 * y0) * (gt + gj + c13)
                           + (x1 * x1 + y1 * y1) * (gt + gj - c13);
                }
                local *= lsc[NL] * lsc[NL];
            }
        }
    }

    // deterministic reduction
    #pragma unroll
    for (int off = 16; off; off >>= 1)
        local += __shfl_down_sync(0xffffffffu, local, off);
    if ((tid & 31) == 0) wsum[tid >> 5] = local;
    __syncthreads();
    if (tid == 0) {
        float tot = 0.0f;
        #pragma unroll
        for (int i = 0; i < THREADS / 32; i++) tot += wsum[i];
        // PLANAR complex output: out[0..B) = real (f1), out[B..2B) = imag (f2)
        out[circ * B + b] = tot;
    }
}

extern "C" void kernel_launch(void* const* d_in, const int* in_sizes, int n_in,
                              void* d_out, int out_size)
{
    const float *x, *qx1, *qz1, *c1, *qx2, *qz2, *c2;

    if (n_in >= 7 && in_sizes[0] > 1000) {
        // dict order: x, q_x1, q_z1, c1, q_x2, q_z2, c2
        x   = (const float*)d_in[0];
        qx1 = (const float*)d_in[1];
        qz1 = (const float*)d_in[2];
        c1  = (const float*)d_in[3];
        qx2 = (const float*)d_in[4];
        qz2 = (const float*)d_in[5];
        c2  = (const float*)d_in[6];
    } else if (n_in >= 7 && in_sizes[0] == NQ && in_sizes[1] == NQ) {
        c1  = (const float*)d_in[0];
        c2  = (const float*)d_in[1];
        qx1 = (const float*)d_in[2];
        qx2 = (const float*)d_in[3];
        qz1 = (const float*)d_in[4];
        qz2 = (const float*)d_in[5];
        x   = (const float*)d_in[6];
    } else {
        const float* qs[4] = {0, 0, 0, 0};
        const float* cs[2] = {0, 0};
        const float* xp = 0;
        int nq = 0, nc = 0;
        for (int i = 0; i < n_in; i++) {
            if (in_sizes[i] > 1000)         xp = (const float*)d_in[i];
            else if (in_sizes[i] == NGATES) { if (nq < 4) qs[nq++] = (const float*)d_in[i]; }
            else if (in_sizes[i] == NQ)     { if (nc < 2) cs[nc++] = (const float*)d_in[i]; }
        }
        x = xp; qx1 = qs[0]; qz1 = qs[1]; qx2 = qs[2]; qz2 = qs[3];
        c1 = cs[0]; c2 = cs[1];
    }

    int xsz = 0;
    for (int i = 0; i < n_in; i++) if (in_sizes[i] > xsz) xsz = in_sizes[i];
    const int B = xsz / NQ;  // 256

    cudaFuncSetAttribute(pqc_kernel,
                         cudaFuncAttributeMaxDynamicSharedMemorySize,
                         HALF * sizeof(ulonglong2));   // 128 KB interleaved

    dim3 grid(B, 2);
    pqc_kernel<<<grid, THREADS, HALF * sizeof(ulonglong2)>>>(
        x, qx1, qz1, c1, qx2, qz2, c2, (float*)d_out, B);
}